// round 3
// baseline (speedup 1.0000x reference)
#include <cuda_runtime.h>
#include <cuda_fp16.h>
#include <math.h>

#define NPOS 392
#define KK   288          // K*K*IN_CAPS
#define OC   32
#define PS   16
#define OSZ  512          // OC*PS
#define CEPS 1e-8f
#define LN2PI 1.8378770664093453f
#define NTHREADS 512
#define KH    144         // KK/2

// vote scratch (fp16): 392 * 288 * 512 * 2B = 115.6 MB
__device__ __half g_votes[(size_t)NPOS * KK * OSZ];

extern __shared__ float smem[];

__global__ __launch_bounds__(NTHREADS, 3)
void convcaps_kernel(const float* __restrict__ x,
                     const float* __restrict__ wts,
                     const float* __restrict__ beta_u,
                     const float* __restrict__ beta_a,
                     float* __restrict__ out)
{
    const int n    = blockIdx.x;
    const int tid  = threadIdx.x;
    const int lane = tid & 31;
    const int wid  = tid >> 5;

    // ---- smem carve (15393 floats ~= 61.6 KB) ----
    float* sP    = smem;            // 4608  poses [k][s]   (aliased by sPart later)
    float* sCk   = sP + KK*PS;      // 288   ck = a/(a+eps)
    float* sR    = sCk + KK;        // 9216  r_hat [k][o]
    float* sMean = sR + KK*OC;      // 544   mean [o*17+s]
    float* sIv   = sMean + 544;     // 544   1/(2 std^2)
    float* sRs0  = sIv + 544;       // 32    rsum ping
    float* sRs1  = sRs0 + 32;       // 32    rsum pong
    float* sIRs  = sRs1 + 32;       // 32
    float* sS1   = sIRs + 32;       // 32
    float* sAct  = sS1 + 32;        // 32
    float* sC    = sAct + 32;       // 32
    float* sCkS  = sC + 32;         // 1     sum of ck
    float* sPart = sP;              // 1024  (reuse of sP region after vote gen)

    if (tid == 0) *sCkS = 0.f;
    __syncthreads();

    // ---- Phase 0: gather input tile (matches reference reshape semantics) ----
    const int b = n / 49;
    const int m = n - b*49;
    for (int idx = tid; idx < 9*544; idx += NTHREADS) {
        int j   = idx / 544;
        int c   = idx - j*544;
        int t9  = 9*m + j;
        int khw = t9 / 49;
        int oyx = t9 - khw*49;
        int oy  = oyx / 7;
        int ox  = oyx - oy*7;
        int kh  = khw / 3;
        int kw  = khw - kh*3;
        int h   = 2*oy + kh;
        int w   = 2*ox + kw;
        float v = x[(size_t)(((b*16 + h)*16) + w)*544 + c];
        if (c < 512) {
            sP[j*512 + c] = v;
        } else {
            float ck = v / (v + CEPS);
            sCk[j*32 + (c - 512)] = ck;
            atomicAdd(sCkS, ck);
        }
    }
    __syncthreads();

    // r_hat init (iteration 0, exact): r_hat = ck/32 ; rsum[o] = sum_k ck/32
    for (int i = tid; i < KK*OC; i += NTHREADS) sR[i] = sCk[i >> 5] * 0.03125f;
    if (tid < 32) sRs0[tid] = (*sCkS) * 0.03125f;

    // ---- Phase 1: votes v[k,o,:] = p[k,:] (4x4) @ W[k,o] (4x4), fp16 store ----
    __half* vbase = g_votes + (size_t)n * (KK*OSZ);
    for (int pair = tid; pair < KK*OC; pair += NTHREADS) {
        int k = pair >> 5;
        const float* p = sP + k*PS;
        const float4* wv4 = (const float4*)(wts + (size_t)pair*16);
        float w0[16];
        #pragma unroll
        for (int q = 0; q < 4; ++q) {
            float4 t = wv4[q];
            w0[4*q+0]=t.x; w0[4*q+1]=t.y; w0[4*q+2]=t.z; w0[4*q+3]=t.w;
        }
        __half2 hh[8];
        #pragma unroll
        for (int i = 0; i < 4; ++i) {
            float p0=p[i*4+0], p1=p[i*4+1], p2=p[i*4+2], p3=p[i*4+3];
            float r0 = p0*w0[0] + p1*w0[4] + p2*w0[8]  + p3*w0[12];
            float r1 = p0*w0[1] + p1*w0[5] + p2*w0[9]  + p3*w0[13];
            float r2 = p0*w0[2] + p1*w0[6] + p2*w0[10] + p3*w0[14];
            float r3 = p0*w0[3] + p1*w0[7] + p2*w0[11] + p3*w0[15];
            hh[2*i+0] = __floats2half2_rn(r0, r1);
            hh[2*i+1] = __floats2half2_rn(r2, r3);
        }
        uint4* dst = (uint4*)(vbase + (size_t)pair*16);
        uint4 u0, u1;
        u0.x = *(unsigned*)&hh[0]; u0.y = *(unsigned*)&hh[1];
        u0.z = *(unsigned*)&hh[2]; u0.w = *(unsigned*)&hh[3];
        u1.x = *(unsigned*)&hh[4]; u1.y = *(unsigned*)&hh[5];
        u1.z = *(unsigned*)&hh[6]; u1.w = *(unsigned*)&hh[7];
        dst[0] = u0; dst[1] = u1;
    }
    __syncthreads();

    // ---- EM routing: 3 iterations, no separate r-normalize pass ----
    float lam = 0.001f;
    float* rsCur = sRs0;
    float* rsNxt = sRs1;
    for (int it = 0; it < 3; ++it) {
        lam += 0.0001f;

        if (tid < 32) {
            float rs = rsCur[tid];
            sIRs[tid] = 1.f/(rs + CEPS);
            sS1[tid]  = rs/(rs + CEPS);
        }
        __syncthreads();

        // (b) m-step vote pass: k split in halves across the block.
        {
            const int khalf = tid >> 8;
            const int idx   = tid & 255;
            const int o     = idx >> 3;
            const int sp    = idx & 7;
            const __half2* vp2 = (const __half2*)vbase + idx;
            const float* rp0 = sR + o;
            float m0 = 0.f, m1 = 0.f, q0 = 0.f, q1 = 0.f;
            const int k0 = khalf * KH;
            #pragma unroll 4
            for (int k = k0; k < k0 + KH; ++k) {
                float2 v = __half22float2(vp2[(size_t)k*256]);
                float r  = rp0[k*32];
                m0 += r*v.x; m1 += r*v.y;
                q0 += r*v.x*v.x; q1 += r*v.y*v.y;
            }
            if (khalf) {
                float* pp = sPart + idx*4;
                pp[0]=m0; pp[1]=m1; pp[2]=q0; pp[3]=q1;
            }
            __syncthreads();
            if (khalf) {
                if (idx < 32) rsNxt[idx] = 0.f;     // zero next rsum buffer
            } else {
                const float* pp = sPart + idx*4;
                const float irs = sIRs[o];
                m0 = (m0 + pp[0]) * irs;
                m1 = (m1 + pp[1]) * irs;
                q0 = (q0 + pp[2]) * irs;
                q1 = (q1 + pp[3]) * irs;
                float s1 = sS1[o];
                float v0 = fmaxf(q0 - m0*m0*(2.f - s1), 0.f) + CEPS;
                float v1 = fmaxf(q1 - m1*m1*(2.f - s1), 0.f) + CEPS;
                sMean[o*17 + 2*sp]     = m0;
                sMean[o*17 + 2*sp + 1] = m1;
                sIv[o*17 + 2*sp]       = 0.5f/v0;
                sIv[o*17 + 2*sp + 1]   = 0.5f/v1;
                float sl = 0.5f*(__logf(v0) + __logf(v1));
                #pragma unroll
                for (int off = 1; off < 8; off <<= 1)
                    sl += __shfl_xor_sync(0xffffffffu, sl, off);
                if (sp == 0) {
                    float cost = (16.f*beta_u[o] + sl) * rsCur[o];
                    float z = lam * (beta_a[o] - cost);
                    float a = 1.f/(1.f + __expf(-z));
                    sAct[o] = a;
                    sC[o]   = __logf(a) - sl - 8.f*LN2PI;
                }
            }
        }
        __syncthreads();

        if (it == 2) break;

        // (c) e-step: r_hat = softmax_o(lnap) * ck ; accumulate rsum[o]
        {
            __half2 mh[8], ivh[8];
            #pragma unroll
            for (int q = 0; q < 8; ++q) {
                mh[q]  = __floats2half2_rn(sMean[lane*17 + 2*q], sMean[lane*17 + 2*q+1]);
                ivh[q] = __floats2half2_rn(sIv[lane*17 + 2*q],   sIv[lane*17 + 2*q+1]);
            }
            const float Co = sC[lane];
            const uint4* vr = (const uint4*)vbase;
            float racc = 0.f;
            for (int k = wid; k < KK; k += 16) {
                uint4 u0 = vr[(size_t)(k*32 + lane)*2];
                uint4 u1 = vr[(size_t)(k*32 + lane)*2 + 1];
                float acc = 0.f;
                #pragma unroll
                for (int h = 0; h < 8; ++h) {
                    unsigned u = (h < 4) ? ((const unsigned*)&u0)[h]
                                         : ((const unsigned*)&u1)[h-4];
                    float2 f  = __half22float2(*(__half2*)&u);
                    float2 mm = __half22float2(mh[h]);
                    float2 iv = __half22float2(ivh[h]);
                    float d0 = f.x - mm.x;
                    float d1 = f.y - mm.y;
                    acc += d0*d0*iv.x + d1*d1*iv.y;
                }
                float lnap = Co - acc;
                float mx = lnap;
                #pragma unroll
                for (int off = 16; off; off >>= 1)
                    mx = fmaxf(mx, __shfl_xor_sync(0xffffffffu, mx, off));
                float e  = __expf(lnap - mx);
                float se = e;
                #pragma unroll
                for (int off = 16; off; off >>= 1)
                    se += __shfl_xor_sync(0xffffffffu, se, off);
                float rh = (e/se) * sCk[k];   // exact: r*a normalized over o
                sR[k*32 + lane] = rh;
                racc += rh;
            }
            atomicAdd(&rsNxt[lane], racc);
        }
        __syncthreads();

        { float* t = rsCur; rsCur = rsNxt; rsNxt = t; }
    }

    // ---- output: [n, 544] = concat(mean[32*16], act[32]) ----
    {
        int o = tid >> 4, s = tid & 15;
        out[(size_t)n*544 + tid] = sMean[o*17 + s];
        if (tid < 32)
            out[(size_t)n*544 + 512 + tid] = sAct[tid];
    }
}

extern "C" void kernel_launch(void* const* d_in, const int* in_sizes, int n_in,
                              void* d_out, int out_size)
{
    const float* x  = (const float*)d_in[0];
    const float* w  = (const float*)d_in[1];
    const float* bu = (const float*)d_in[2];
    const float* ba = (const float*)d_in[3];
    float* out = (float*)d_out;

    const int smem_bytes = 15396 * 4;   // ~61.6 KB -> 3 CTAs/SM
    cudaFuncSetAttribute(convcaps_kernel,
                         cudaFuncAttributeMaxDynamicSharedMemorySize, smem_bytes);
    convcaps_kernel<<<NPOS, NTHREADS, smem_bytes>>>(x, w, bu, ba, out);
}